// round 5
// baseline (speedup 1.0000x reference)
#include <cuda_runtime.h>
#include <math.h>

#define H_   96
#define W_   128
#define C_   21
#define N_   (H_*W_)
#define RAD  16
#define TAPS 33
#define GRID 148
#define NTHR 512
#define PPW  168            // padded row stride for hconv (>= 164)

// Scratch (__device__ globals: allocation-free rule)
__device__ float g_tmp[C_*N_];            // after horizontal conv
__device__ float g_s[C_*N_];              // after vertical conv
__device__ volatile unsigned g_flags[GRID];  // per-block barrier phase flags

// Flag-array grid barrier: no atomic serialization. Safe: GRID=148 <= SM count,
// 1 CTA/SM resident. Phases are base-relative so graph replays work.
__device__ __forceinline__ void grid_bar(unsigned phase, int t, int bid) {
    __syncthreads();
    if (t == 0) {
        __threadfence();            // publish this block's writes before flag
        g_flags[bid] = phase;
    }
    if (t < GRID) {
        while ((int)(g_flags[t] - phase) < 0) { }
    }
    __threadfence();
    __syncthreads();
}

// channel split over 4 groups: sizes 6,5,5,5
__device__ __forceinline__ int grp_c0(int g)  { return (g == 0) ? 0 : (1 + 5*g); }
__device__ __forceinline__ int grp_len(int g) { return (g == 0) ? 6 : 5; }

__global__ __launch_bounds__(NTHR, 1)
void crf_persistent(const float* __restrict__ un,
                    const float* __restrict__ ws,
                    const float* __restrict__ wb,
                    const float* __restrict__ compat,
                    float* __restrict__ out)
{
    __shared__ float sA[C_*C_];
    __shared__ float skx[TAPS];
    __shared__ float sinx[W_];
    __shared__ float siny[H_];
    __shared__ float sv[C_*W_];      // normalized s staging       (2688)
    __shared__ float pp[C_*PPW];     // padded softmax rows        (3528)
    __shared__ float svc[4096];      // vconv tile / q buffer      (4096)

    const int t   = threadIdx.x;
    const int bid = blockIdx.x;
    const unsigned base = g_flags[bid];   // same across all blocks (prev launch)
    unsigned bar_k = 0;

    // ---- per-block init (redundant across blocks; cheap) ----
    if (t < TAPS) skx[t] = expf(-(float)((t-RAD)*(t-RAD)) / 18.0f);
    // zero pp (pads stay zero forever; interior overwritten each iter)
    for (int i = t; i < C_*PPW; i += NTHR) pp[i] = 0.f;
    __syncthreads();
    if (t < W_) {
        float s = 0.f;
        #pragma unroll
        for (int j = 0; j < TAPS; j++) {
            int xp = t + j - RAD;
            if (xp >= 0 && xp < W_) s += skx[j];
        }
        sinx[t] = 1.0f / s;
    }
    if (t >= 128 && t < 128 + H_) {
        int y = t - 128;
        float s = 0.f;
        #pragma unroll
        for (int j = 0; j < TAPS; j++) {
            int yp = y + j - RAD;
            if (yp >= 0 && yp < H_) s += skx[j];
        }
        siny[y] = 1.0f / s;
    }
    for (int idx = t; idx < C_*C_; idx += NTHR) {
        int i = idx / C_, j = idx % C_;
        float a = 0.f;
        #pragma unroll
        for (int k = 0; k < C_; k++)
            a += compat[i*C_ + k] * (ws[k*C_ + j] + wb[k*C_ + j]);
        sA[idx] = a;   // A = compat @ (Ws + Wb); bilateral path is dead (source bug)
    }
    __syncthreads();

    const int y = bid;               // row owned by this block (bid < H_)

    for (int it = 0; it <= 5; it++) {
        // ============ update + softmax + hconv (row y), writes g_tmp ============
        if (bid < H_) {
            if (it > 0) {
                // stage normalized s for this row
                #pragma unroll
                for (int r = 0; r < 6; r++) {
                    int idx = t + r*NTHR;
                    if (idx < C_*W_) {
                        int c = idx >> 7, x = idx & 127;
                        sv[idx] = __ldcv(&g_s[c*N_ + y*W_ + x]) * (sinx[x] * siny[y]);
                    }
                }
                __syncthreads();
                // matvec: 256 threads, 2 pixels each (x, x+64), channel group g
                if (t < 256) {
                    const int x  = t & 63;
                    const int g  = t >> 6;
                    const int c0 = grp_c0(g), ln = grp_len(g);
                    float a0[6], a1[6];
                    #pragma unroll 6
                    for (int ci = 0; ci < 6; ci++) {
                        if (ci >= ln) break;
                        a0[ci] = un[(y*W_ + x)*C_ + c0 + ci];
                        a1[ci] = un[(y*W_ + x + 64)*C_ + c0 + ci];
                    }
                    #pragma unroll
                    for (int cp = 0; cp < C_; cp++) {
                        float s0 = sv[cp*W_ + x];
                        float s1 = sv[cp*W_ + x + 64];
                        #pragma unroll 6
                        for (int ci = 0; ci < 6; ci++) {
                            if (ci >= ln) break;
                            float w = sA[(c0 + ci)*C_ + cp];
                            a0[ci] -= w * s0;
                            a1[ci] -= w * s1;
                        }
                    }
                    #pragma unroll 6
                    for (int ci = 0; ci < 6; ci++) {
                        if (ci >= ln) break;
                        svc[(c0 + ci)*W_ + x]      = a0[ci];
                        svc[(c0 + ci)*W_ + x + 64] = a1[ci];
                    }
                }
                __syncthreads();
            }
            if (it < 5) {
                // softmax per pixel (128 threads); iter 0 reads unaries directly
                if (t < W_) {
                    float v[C_];
                    float m = -1e30f;
                    #pragma unroll
                    for (int c = 0; c < C_; c++) {
                        v[c] = (it == 0) ? un[(y*W_ + t)*C_ + c] : svc[c*W_ + t];
                        m = fmaxf(m, v[c]);
                    }
                    float s = 0.f;
                    #pragma unroll
                    for (int c = 0; c < C_; c++) { v[c] = expf(v[c] - m); s += v[c]; }
                    float inv = 1.0f / s;
                    #pragma unroll
                    for (int c = 0; c < C_; c++) pp[c*PPW + RAD + t] = v[c] * inv;
                }
                __syncthreads();
                // horizontal conv, register-tiled: thread = (c, 6-wide x group)
                if (t < C_*22) {
                    int c  = t / 22;
                    int x0 = (t % 22) * 6;
                    const float* p = pp + c*PPW + x0;
                    float acc[6] = {0.f,0.f,0.f,0.f,0.f,0.f};
                    #pragma unroll
                    for (int i = 0; i < TAPS + 5; i++) {
                        float v = p[i];
                        #pragma unroll
                        for (int r = 0; r < 6; r++) {
                            int j = i - r;
                            if (j >= 0 && j < TAPS) acc[r] += skx[j] * v;
                        }
                    }
                    #pragma unroll
                    for (int r = 0; r < 6; r++)
                        if (x0 + r < W_) g_tmp[c*N_ + y*W_ + x0 + r] = acc[r];
                }
            } else {
                // final: write q to out[0, w, h, c]
                if (t < 256) {
                    const int x  = t & 63;
                    const int g  = t >> 6;
                    const int c0 = grp_c0(g), ln = grp_len(g);
                    #pragma unroll 6
                    for (int ci = 0; ci < 6; ci++) {
                        if (ci >= ln) break;
                        int c = c0 + ci;
                        out[(x*H_ + y)*C_ + c]        = svc[c*W_ + x];
                        out[((x + 64)*H_ + y)*C_ + c] = svc[c*W_ + x + 64];
                    }
                }
            }
        }
        if (it == 5) break;
        grid_bar(base + (++bar_k), t, bid);

        // ============ vertical conv: unit = (class, 32-wide x tile), 84 units ======
        if (bid < C_*4) {
            const int c  = bid >> 2;
            const int x0 = (bid & 3) << 5;
            #pragma unroll
            for (int r = 0; r < 8; r++) {           // 128 padded rows x 32 cols
                int idx = t + r*NTHR;
                int yy = idx >> 5, xx = idx & 31;
                int yv = yy - RAD;
                svc[idx] = (yv >= 0 && yv < H_) ? __ldcv(&g_tmp[c*N_ + yv*W_ + x0 + xx]) : 0.f;
            }
            __syncthreads();
            const int xx = t & 31;
            const int y0 = (t >> 5) * 6;            // 16 y-groups x 6 rows = 96
            const float* bp = svc + y0*32 + xx;
            float acc[6] = {0.f,0.f,0.f,0.f,0.f,0.f};
            #pragma unroll
            for (int i = 0; i < TAPS + 5; i++) {
                float v = bp[i*32];
                #pragma unroll
                for (int r = 0; r < 6; r++) {
                    int j = i - r;
                    if (j >= 0 && j < TAPS) acc[r] += skx[j] * v;
                }
            }
            #pragma unroll
            for (int r = 0; r < 6; r++)
                g_s[c*N_ + (y0 + r)*W_ + x0 + xx] = acc[r];
        }
        grid_bar(base + (++bar_k), t, bid);
    }
}

extern "C" void kernel_launch(void* const* d_in, const int* in_sizes, int n_in,
                              void* d_out, int out_size) {
    const float* un     = (const float*)d_in[0];
    // d_in[1] = rgb : provably unused (bilateral output discarded by replicated source bug)
    const float* ws     = (const float*)d_in[2];
    const float* wb     = (const float*)d_in[3];
    const float* compat = (const float*)d_in[4];
    float* out = (float*)d_out;

    crf_persistent<<<GRID, NTHR>>>(un, ws, wb, compat, out);
}

// round 6
// speedup vs baseline: 1.4221x; 1.4221x over previous
#include <cuda_runtime.h>
#include <math.h>

#define H_   96
#define W_   128
#define C_   21
#define N_   (H_*W_)
#define RAD  16
#define TAPS 33
#define GRID 148
#define NTHR 512
#define PPW  168            // padded row stride for hconv (>= 164)

// Scratch (__device__ globals: allocation-free rule)
__device__ float g_tmp[C_*N_];               // after horizontal conv
__device__ float g_s[C_*N_];                 // after vertical conv
__device__ volatile unsigned g_arr[GRID];    // per-block arrive counters
__device__ volatile unsigned g_release;      // aggregated release counter

// Two-level grid barrier: parallel flag stores, block 0 aggregates, single
// release word. nanosleep backoff keeps poll traffic off the L2 critical path.
// Safe: GRID=148 <= SM count, 1 CTA/SM -> all blocks resident.
__device__ __forceinline__ void grid_bar(unsigned target, int t, int bid) {
    __syncthreads();
    if (t == 0) {
        __threadfence();              // publish this block's data writes
        g_arr[bid] = target;          // parallel arrive, no atomic
    }
    if (bid == 0) {
        if (t < GRID) {
            while ((int)(g_arr[t] - target) < 0) __nanosleep(30);
        }
        __syncthreads();              // all 148 flags seen
        if (t == 0) {
            __threadfence();
            g_release = target;       // single release word
        }
    } else {
        if (t == 0) {
            while ((int)(g_release - target) < 0) __nanosleep(30);
        }
    }
    __threadfence();
    __syncthreads();
}

// channel split over 4 groups: sizes 6,5,5,5
__device__ __forceinline__ int grp_c0(int g)  { return (g == 0) ? 0 : (1 + 5*g); }
__device__ __forceinline__ int grp_len(int g) { return (g == 0) ? 6 : 5; }

__global__ __launch_bounds__(NTHR, 1)
void crf_persistent(const float* __restrict__ un,
                    const float* __restrict__ ws,
                    const float* __restrict__ wb,
                    const float* __restrict__ compat,
                    float* __restrict__ out)
{
    __shared__ float sA[C_*C_];
    __shared__ float skx[TAPS];
    __shared__ float sinx[W_];
    __shared__ float siny[H_];
    __shared__ float sv[C_*W_];      // normalized s staging       (2688)
    __shared__ float pp[C_*PPW];     // padded softmax rows        (3528)
    __shared__ float svc[4096];      // vconv tile / q buffer      (4096)

    const int t   = threadIdx.x;
    const int bid = blockIdx.x;
    const unsigned base = g_release;  // consistent across blocks (prev launch done)
    unsigned bar_k = 0;

    // ---- per-block init (redundant across blocks; cheap) ----
    if (t < TAPS) skx[t] = expf(-(float)((t-RAD)*(t-RAD)) / 18.0f);
    for (int i = t; i < C_*PPW; i += NTHR) pp[i] = 0.f;   // pads stay zero forever
    __syncthreads();
    if (t < W_) {
        float s = 0.f;
        #pragma unroll
        for (int j = 0; j < TAPS; j++) {
            int xp = t + j - RAD;
            if (xp >= 0 && xp < W_) s += skx[j];
        }
        sinx[t] = 1.0f / s;
    }
    if (t >= 128 && t < 128 + H_) {
        int y = t - 128;
        float s = 0.f;
        #pragma unroll
        for (int j = 0; j < TAPS; j++) {
            int yp = y + j - RAD;
            if (yp >= 0 && yp < H_) s += skx[j];
        }
        siny[y] = 1.0f / s;
    }
    for (int idx = t; idx < C_*C_; idx += NTHR) {
        int i = idx / C_, j = idx % C_;
        float a = 0.f;
        #pragma unroll
        for (int k = 0; k < C_; k++)
            a += compat[i*C_ + k] * (ws[k*C_ + j] + wb[k*C_ + j]);
        sA[idx] = a;   // A = compat @ (Ws + Wb); bilateral path is dead (source bug)
    }
    __syncthreads();

    const int y = bid;               // row owned by this block (bid < H_)

    for (int it = 0; it <= 5; it++) {
        // ============ update + softmax + hconv (row y), writes g_tmp ============
        if (bid < H_) {
            if (it > 0) {
                // stage normalized s for this row
                #pragma unroll
                for (int r = 0; r < 6; r++) {
                    int idx = t + r*NTHR;
                    if (idx < C_*W_) {
                        int c = idx >> 7, x = idx & 127;
                        sv[idx] = __ldcv(&g_s[c*N_ + y*W_ + x]) * (sinx[x] * siny[y]);
                    }
                }
                __syncthreads();
                // matvec: 256 threads, 2 pixels each (x, x+64), channel group g
                if (t < 256) {
                    const int x  = t & 63;
                    const int g  = t >> 6;
                    const int c0 = grp_c0(g), ln = grp_len(g);
                    float a0[6], a1[6];
                    #pragma unroll 6
                    for (int ci = 0; ci < 6; ci++) {
                        if (ci >= ln) break;
                        a0[ci] = un[(y*W_ + x)*C_ + c0 + ci];
                        a1[ci] = un[(y*W_ + x + 64)*C_ + c0 + ci];
                    }
                    #pragma unroll
                    for (int cp = 0; cp < C_; cp++) {
                        float s0 = sv[cp*W_ + x];
                        float s1 = sv[cp*W_ + x + 64];
                        #pragma unroll 6
                        for (int ci = 0; ci < 6; ci++) {
                            if (ci >= ln) break;
                            float w = sA[(c0 + ci)*C_ + cp];
                            a0[ci] -= w * s0;
                            a1[ci] -= w * s1;
                        }
                    }
                    #pragma unroll 6
                    for (int ci = 0; ci < 6; ci++) {
                        if (ci >= ln) break;
                        svc[(c0 + ci)*W_ + x]      = a0[ci];
                        svc[(c0 + ci)*W_ + x + 64] = a1[ci];
                    }
                }
                __syncthreads();
            }
            if (it < 5) {
                // softmax per pixel (128 threads); iter 0 reads unaries directly
                if (t < W_) {
                    float v[C_];
                    float m = -1e30f;
                    #pragma unroll
                    for (int c = 0; c < C_; c++) {
                        v[c] = (it == 0) ? un[(y*W_ + t)*C_ + c] : svc[c*W_ + t];
                        m = fmaxf(m, v[c]);
                    }
                    float s = 0.f;
                    #pragma unroll
                    for (int c = 0; c < C_; c++) { v[c] = expf(v[c] - m); s += v[c]; }
                    float inv = 1.0f / s;
                    #pragma unroll
                    for (int c = 0; c < C_; c++) pp[c*PPW + RAD + t] = v[c] * inv;
                }
                __syncthreads();
                // horizontal conv, register-tiled: thread = (c, 6-wide x group)
                if (t < C_*22) {
                    int c  = t / 22;
                    int x0 = (t % 22) * 6;
                    const float* p = pp + c*PPW + x0;
                    float acc[6] = {0.f,0.f,0.f,0.f,0.f,0.f};
                    #pragma unroll
                    for (int i = 0; i < TAPS + 5; i++) {
                        float v = p[i];
                        #pragma unroll
                        for (int r = 0; r < 6; r++) {
                            int j = i - r;
                            if (j >= 0 && j < TAPS) acc[r] += skx[j] * v;
                        }
                    }
                    #pragma unroll
                    for (int r = 0; r < 6; r++)
                        if (x0 + r < W_) g_tmp[c*N_ + y*W_ + x0 + r] = acc[r];
                }
            } else {
                // final: write q to out[0, w, h, c]
                if (t < 256) {
                    const int x  = t & 63;
                    const int g  = t >> 6;
                    const int c0 = grp_c0(g), ln = grp_len(g);
                    #pragma unroll 6
                    for (int ci = 0; ci < 6; ci++) {
                        if (ci >= ln) break;
                        int c = c0 + ci;
                        out[(x*H_ + y)*C_ + c]        = svc[c*W_ + x];
                        out[((x + 64)*H_ + y)*C_ + c] = svc[c*W_ + x + 64];
                    }
                }
            }
        }
        if (it == 5) break;
        grid_bar(base + (++bar_k), t, bid);

        // ============ vertical conv: unit = (class, 32-wide x tile), 84 units ======
        if (bid < C_*4) {
            const int c  = bid >> 2;
            const int x0 = (bid & 3) << 5;
            #pragma unroll
            for (int r = 0; r < 8; r++) {           // 128 padded rows x 32 cols
                int idx = t + r*NTHR;
                int yy = idx >> 5, xx = idx & 31;
                int yv = yy - RAD;
                svc[idx] = (yv >= 0 && yv < H_) ? __ldcv(&g_tmp[c*N_ + yv*W_ + x0 + xx]) : 0.f;
            }
            __syncthreads();
            const int xx = t & 31;
            const int y0 = (t >> 5) * 6;            // 16 y-groups x 6 rows = 96
            const float* bp = svc + y0*32 + xx;
            float acc[6] = {0.f,0.f,0.f,0.f,0.f,0.f};
            #pragma unroll
            for (int i = 0; i < TAPS + 5; i++) {
                float v = bp[i*32];
                #pragma unroll
                for (int r = 0; r < 6; r++) {
                    int j = i - r;
                    if (j >= 0 && j < TAPS) acc[r] += skx[j] * v;
                }
            }
            #pragma unroll
            for (int r = 0; r < 6; r++)
                g_s[c*N_ + (y0 + r)*W_ + x0 + xx] = acc[r];
        }
        grid_bar(base + (++bar_k), t, bid);
    }
}

extern "C" void kernel_launch(void* const* d_in, const int* in_sizes, int n_in,
                              void* d_out, int out_size) {
    const float* un     = (const float*)d_in[0];
    // d_in[1] = rgb : provably unused (bilateral output discarded by replicated source bug)
    const float* ws     = (const float*)d_in[2];
    const float* wb     = (const float*)d_in[3];
    const float* compat = (const float*)d_in[4];
    float* out = (float*)d_out;

    crf_persistent<<<GRID, NTHR>>>(un, ws, wb, compat, out);
}

// round 7
// speedup vs baseline: 1.4272x; 1.0036x over previous
#include <cuda_runtime.h>
#include <math.h>

#define H_   96
#define W_   128
#define C_   21
#define N_   (H_*W_)
#define RAD  16
#define TAPS 33
#define GRID 148
#define NTHR 512
#define PPW  168            // padded row stride for hconv (>= 164)
#define NSUB 8

// Scratch (__device__ globals: allocation-free rule)
__device__ float g_tmp[C_*N_];               // after horizontal conv
__device__ float g_s[C_*N_];                 // after vertical conv
__device__ unsigned g_sub[NSUB*32];          // sub-counters, 128B apart
__device__ unsigned g_master;
__device__ volatile unsigned g_release;      // free-running release counter

// Single-phase two-level grid barrier. 8-way parallel atomic arrive
// (~19 serialized RMW per line), last master-arriver resets counters and
// publishes the release word; waiters tight-spin (1 poller/block on 1 line).
// Safe: GRID=148 <= SM count, 1 CTA/SM -> all blocks resident.
__device__ __forceinline__ void grid_bar(unsigned target, int t, int bid) {
    __syncthreads();
    if (t == 0) {
        __threadfence();                          // publish this block's writes
        const int r = bid & (NSUB - 1);
        const unsigned cnt = (r < 4) ? 19u : 18u; // 4*19 + 4*18 = 148
        if (atomicAdd(&g_sub[r*32], 1u) == cnt - 1u) {
            if (atomicAdd(&g_master, 1u) == NSUB - 1u) {
                #pragma unroll
                for (int i = 0; i < NSUB; i++) atomicExch(&g_sub[i*32], 0u);
                atomicExch(&g_master, 0u);
                __threadfence();
                g_release = target;               // single-phase release
            }
        }
        while ((int)(g_release - target) < 0) { } // tight spin, no sleep
        __threadfence();
    }
    __syncthreads();
}

// channel split over 4 groups: sizes 6,5,5,5
__device__ __forceinline__ int grp_c0(int g)  { return (g == 0) ? 0 : (1 + 5*g); }
__device__ __forceinline__ int grp_len(int g) { return (g == 0) ? 6 : 5; }

__global__ __launch_bounds__(NTHR, 1)
void crf_persistent(const float* __restrict__ un,
                    const float* __restrict__ ws,
                    const float* __restrict__ wb,
                    const float* __restrict__ compat,
                    float* __restrict__ out)
{
    __shared__ float sA[C_*C_];
    __shared__ float skx[TAPS];
    __shared__ float sinx[W_];
    __shared__ float siny[H_];
    __shared__ float sv[C_*W_];      // normalized s staging       (2688)
    __shared__ float pp[C_*PPW];     // padded softmax rows        (3528)
    __shared__ float svc[4096];      // vconv tile / q buffer      (4096)

    const int t   = threadIdx.x;
    const int bid = blockIdx.x;
    const unsigned base = g_release;  // settled value from previous launch
    unsigned bar_k = 0;

    // ---- per-block init (redundant across blocks; cheap) ----
    if (t < TAPS) skx[t] = expf(-(float)((t-RAD)*(t-RAD)) / 18.0f);
    for (int i = t; i < C_*PPW; i += NTHR) pp[i] = 0.f;   // pads stay zero forever
    __syncthreads();
    if (t < W_) {
        float s = 0.f;
        #pragma unroll
        for (int j = 0; j < TAPS; j++) {
            int xp = t + j - RAD;
            if (xp >= 0 && xp < W_) s += skx[j];
        }
        sinx[t] = 1.0f / s;
    }
    if (t >= 128 && t < 128 + H_) {
        int y = t - 128;
        float s = 0.f;
        #pragma unroll
        for (int j = 0; j < TAPS; j++) {
            int yp = y + j - RAD;
            if (yp >= 0 && yp < H_) s += skx[j];
        }
        siny[y] = 1.0f / s;
    }
    for (int idx = t; idx < C_*C_; idx += NTHR) {
        int i = idx / C_, j = idx % C_;
        float a = 0.f;
        #pragma unroll
        for (int k = 0; k < C_; k++)
            a += compat[i*C_ + k] * (ws[k*C_ + j] + wb[k*C_ + j]);
        sA[idx] = a;   // A = compat @ (Ws + Wb); bilateral path is dead (source bug)
    }
    __syncthreads();

    const int y = bid;               // row owned by this block (bid < H_)

    for (int it = 0; it <= 5; it++) {
        // ============ update + softmax + hconv (row y), writes g_tmp ============
        if (bid < H_) {
            if (it > 0) {
                // stage normalized s for this row
                #pragma unroll
                for (int r = 0; r < 6; r++) {
                    int idx = t + r*NTHR;
                    if (idx < C_*W_) {
                        int c = idx >> 7, x = idx & 127;
                        sv[idx] = __ldcv(&g_s[c*N_ + y*W_ + x]) * (sinx[x] * siny[y]);
                    }
                }
                __syncthreads();
                // matvec: 512 threads, 1 pixel x channel-group each
                {
                    const int x  = t & 127;
                    const int g  = t >> 7;
                    const int c0 = grp_c0(g), ln = grp_len(g);
                    float q[6];
                    #pragma unroll 6
                    for (int ci = 0; ci < 6; ci++) {
                        if (ci >= ln) break;
                        q[ci] = un[(y*W_ + x)*C_ + c0 + ci];
                    }
                    #pragma unroll
                    for (int cp = 0; cp < C_; cp++) {
                        float s0 = sv[cp*W_ + x];
                        #pragma unroll 6
                        for (int ci = 0; ci < 6; ci++) {
                            if (ci >= ln) break;
                            q[ci] -= sA[(c0 + ci)*C_ + cp] * s0;
                        }
                    }
                    if (it < 5) {
                        #pragma unroll 6
                        for (int ci = 0; ci < 6; ci++) {
                            if (ci >= ln) break;
                            svc[(c0 + ci)*W_ + x] = q[ci];
                        }
                    } else {
                        // final: write q straight to out[0, w, h, c]
                        #pragma unroll 6
                        for (int ci = 0; ci < 6; ci++) {
                            if (ci >= ln) break;
                            out[(x*H_ + y)*C_ + c0 + ci] = q[ci];
                        }
                    }
                }
                __syncthreads();
            }
            if (it < 5) {
                // softmax per pixel (128 threads); iter 0 reads unaries directly
                if (t < W_) {
                    float v[C_];
                    float m = -1e30f;
                    #pragma unroll
                    for (int c = 0; c < C_; c++) {
                        v[c] = (it == 0) ? un[(y*W_ + t)*C_ + c] : svc[c*W_ + t];
                        m = fmaxf(m, v[c]);
                    }
                    float s = 0.f;
                    #pragma unroll
                    for (int c = 0; c < C_; c++) { v[c] = expf(v[c] - m); s += v[c]; }
                    float inv = 1.0f / s;
                    #pragma unroll
                    for (int c = 0; c < C_; c++) pp[c*PPW + RAD + t] = v[c] * inv;
                }
                __syncthreads();
                // horizontal conv, register-tiled: thread = (c, 6-wide x group)
                if (t < C_*22) {
                    int c  = t / 22;
                    int x0 = (t % 22) * 6;
                    const float* p = pp + c*PPW + x0;
                    float acc[6] = {0.f,0.f,0.f,0.f,0.f,0.f};
                    #pragma unroll
                    for (int i = 0; i < TAPS + 5; i++) {
                        float v = p[i];
                        #pragma unroll
                        for (int r = 0; r < 6; r++) {
                            int j = i - r;
                            if (j >= 0 && j < TAPS) acc[r] += skx[j] * v;
                        }
                    }
                    #pragma unroll
                    for (int r = 0; r < 6; r++)
                        if (x0 + r < W_) g_tmp[c*N_ + y*W_ + x0 + r] = acc[r];
                }
            }
        }
        if (it == 5) break;
        grid_bar(base + (++bar_k), t, bid);

        // ============ vertical conv: unit = (class, 32-wide x tile), 84 units ======
        if (bid < C_*4) {
            const int c  = bid >> 2;
            const int x0 = (bid & 3) << 5;
            #pragma unroll
            for (int r = 0; r < 8; r++) {           // 128 padded rows x 32 cols
                int idx = t + r*NTHR;
                int yy = idx >> 5, xx = idx & 31;
                int yv = yy - RAD;
                svc[idx] = (yv >= 0 && yv < H_) ? __ldcv(&g_tmp[c*N_ + yv*W_ + x0 + xx]) : 0.f;
            }
            __syncthreads();
            const int xx = t & 31;
            const int y0 = (t >> 5) * 6;            // 16 y-groups x 6 rows = 96
            const float* bp = svc + y0*32 + xx;
            float acc[6] = {0.f,0.f,0.f,0.f,0.f,0.f};
            #pragma unroll
            for (int i = 0; i < TAPS + 5; i++) {
                float v = bp[i*32];
                #pragma unroll
                for (int r = 0; r < 6; r++) {
                    int j = i - r;
                    if (j >= 0 && j < TAPS) acc[r] += skx[j] * v;
                }
            }
            #pragma unroll
            for (int r = 0; r < 6; r++)
                g_s[c*N_ + (y0 + r)*W_ + x0 + xx] = acc[r];
        }
        grid_bar(base + (++bar_k), t, bid);
    }
}

extern "C" void kernel_launch(void* const* d_in, const int* in_sizes, int n_in,
                              void* d_out, int out_size) {
    const float* un     = (const float*)d_in[0];
    // d_in[1] = rgb : provably unused (bilateral output discarded by replicated source bug)
    const float* ws     = (const float*)d_in[2];
    const float* wb     = (const float*)d_in[3];
    const float* compat = (const float*)d_in[4];
    float* out = (float*)d_out;

    crf_persistent<<<GRID, NTHR>>>(un, ws, wb, compat, out);
}

// round 8
// speedup vs baseline: 1.4770x; 1.0349x over previous
#include <cuda_runtime.h>
#include <math.h>

#define H_   96
#define W_   128
#define C_   21
#define N_   (H_*W_)
#define RAD  16
#define TAPS 33
#define GRID 96           // one block per image row; all resident (<=148 SMs)
#define NTHR 512
#define PPW  168          // padded row stride for hconv (>= 164)
#define NSUB 8

// Scratch (__device__ globals: allocation-free rule)
__device__ float g_tmp[2][C_*N_];            // double-buffered hconv output
__device__ unsigned g_sub[NSUB*32];          // barrier sub-counters, 128B apart
__device__ unsigned g_master;
__device__ volatile unsigned g_release;      // free-running release counter

// Single-phase two-level grid barrier (96 = 8 x 12 arrivals).
__device__ __forceinline__ void grid_bar(unsigned target, int t, int bid) {
    __syncthreads();
    if (t == 0) {
        __threadfence();                          // publish this block's writes
        const int r = bid & (NSUB - 1);
        if (atomicAdd(&g_sub[r*32], 1u) == (GRID/NSUB) - 1u) {
            if (atomicAdd(&g_master, 1u) == NSUB - 1u) {
                #pragma unroll
                for (int i = 0; i < NSUB; i++) atomicExch(&g_sub[i*32], 0u);
                atomicExch(&g_master, 0u);
                __threadfence();
                g_release = target;               // single-phase release
            }
        }
        while ((int)(g_release - target) < 0) { }
        __threadfence();
    }
    __syncthreads();
}

// channel split over 4 groups: sizes 6,5,5,5
__device__ __forceinline__ int grp_c0(int g)  { return (g == 0) ? 0 : (1 + 5*g); }
__device__ __forceinline__ int grp_len(int g) { return (g == 0) ? 6 : 5; }

__global__ __launch_bounds__(NTHR, 1)
void crf_persistent(const float* __restrict__ un,
                    const float* __restrict__ ws,
                    const float* __restrict__ wb,
                    const float* __restrict__ compat,
                    float* __restrict__ out)
{
    __shared__ float sA[C_*C_];
    __shared__ float skx[TAPS];
    __shared__ float sinx[W_];
    __shared__ float s_siny;          // siny for this block's row only
    __shared__ float s_un[C_*W_];     // this row's unaries, channel-major
    __shared__ float s_sv[C_*W_];     // normalized vconv output
    __shared__ float pp[C_*PPW];      // q / softmax rows, conv-padded

    const int t   = threadIdx.x;
    const int y   = blockIdx.x;       // this block's image row
    const unsigned base = g_release;  // settled from previous launch
    unsigned bar_k = 0;

    // ---- per-block init ----
    if (t < TAPS) skx[t] = expf(-(float)((t-RAD)*(t-RAD)) / 18.0f);
    for (int i = t; i < C_*PPW; i += NTHR) pp[i] = 0.f;   // pads stay zero
    __syncthreads();
    if (t < W_) {
        float s = 0.f;
        #pragma unroll
        for (int j = 0; j < TAPS; j++) {
            int xp = t + j - RAD;
            if (xp >= 0 && xp < W_) s += skx[j];
        }
        sinx[t] = 1.0f / s;
    }
    if (t == NTHR-1) {
        float s = 0.f;
        #pragma unroll
        for (int j = 0; j < TAPS; j++) {
            int yp = y + j - RAD;
            if (yp >= 0 && yp < H_) s += skx[j];
        }
        s_siny = 1.0f / s;
    }
    for (int idx = t; idx < C_*C_; idx += NTHR) {
        int i = idx / C_, j = idx % C_;
        float a = 0.f;
        #pragma unroll
        for (int k = 0; k < C_; k++)
            a += compat[i*C_ + k] * (ws[k*C_ + j] + wb[k*C_ + j]);
        sA[idx] = a;   // A = compat @ (Ws + Wb); bilateral path is dead (source bug)
    }
    // cache this row's unaries: un[y*W*C + x*C + c] -> s_un[c*W + x]
    {
        const float* ub = un + y*W_*C_;
        for (int i = t; i < C_*W_; i += NTHR) {
            int x = i / C_, c = i - x*C_;
            s_un[c*W_ + x] = ub[i];
        }
    }
    __syncthreads();

    // ===== iteration 0: softmax(unaries) + hconv -> g_tmp[0] =====
    if (t < W_) {
        float v[C_];
        float m = -1e30f;
        #pragma unroll
        for (int c = 0; c < C_; c++) { v[c] = s_un[c*W_ + t]; m = fmaxf(m, v[c]); }
        float s = 0.f;
        #pragma unroll
        for (int c = 0; c < C_; c++) { v[c] = expf(v[c] - m); s += v[c]; }
        float inv = 1.0f / s;
        #pragma unroll
        for (int c = 0; c < C_; c++) pp[c*PPW + RAD + t] = v[c] * inv;
    }
    __syncthreads();
    if (t < C_*22) {                              // hconv, 6 outputs/thread
        int c  = t / 22;
        int x0 = (t % 22) * 6;
        const float* p = pp + c*PPW + x0;
        float acc[6] = {0.f,0.f,0.f,0.f,0.f,0.f};
        #pragma unroll
        for (int i = 0; i < TAPS + 5; i++) {
            float v = p[i];
            #pragma unroll
            for (int r = 0; r < 6; r++) {
                int j = i - r;
                if (j >= 0 && j < TAPS) acc[r] += skx[j] * v;
            }
        }
        #pragma unroll
        for (int r = 0; r < 6; r++)
            if (x0 + r < W_) g_tmp[0][c*N_ + y*W_ + x0 + r] = acc[r];
    }
    grid_bar(base + (++bar_k), t, y);

    // ===== iterations 1..5: vconv + update (+ softmax + hconv) =====
    for (int it = 1; it <= 5; it++) {
        const int rb = (it - 1) & 1;
        const int wb_ = it & 1;

        // vconv over this row: item = (c, 4-wide x), 672 items
        const float nys = s_siny;
        for (int u = t; u < C_*(W_/4); u += NTHR) {
            int c  = u >> 5;
            int x4 = (u & 31) << 2;
            float4 acc = make_float4(0.f, 0.f, 0.f, 0.f);
            #pragma unroll
            for (int j = 0; j < TAPS; j++) {
                int yy = y + j - RAD;
                if (yy >= 0 && yy < H_) {
                    float4 v = __ldcv((const float4*)&g_tmp[rb][(c*H_ + yy)*W_ + x4]);
                    float k = skx[j];
                    acc.x += k*v.x; acc.y += k*v.y; acc.z += k*v.z; acc.w += k*v.w;
                }
            }
            s_sv[c*W_ + x4 + 0] = acc.x * (sinx[x4 + 0] * nys);
            s_sv[c*W_ + x4 + 1] = acc.y * (sinx[x4 + 1] * nys);
            s_sv[c*W_ + x4 + 2] = acc.z * (sinx[x4 + 2] * nys);
            s_sv[c*W_ + x4 + 3] = acc.w * (sinx[x4 + 3] * nys);
        }
        __syncthreads();

        // update matvec: thread = (x, channel-group); q -> pp (or out on last iter)
        {
            const int x  = t & 127;
            const int g  = t >> 7;
            const int c0 = grp_c0(g), ln = grp_len(g);
            float q[6];
            #pragma unroll 6
            for (int ci = 0; ci < 6; ci++) {
                if (ci >= ln) break;
                q[ci] = s_un[(c0 + ci)*W_ + x];
            }
            #pragma unroll
            for (int cp = 0; cp < C_; cp++) {
                float s0 = s_sv[cp*W_ + x];
                #pragma unroll 6
                for (int ci = 0; ci < 6; ci++) {
                    if (ci >= ln) break;
                    q[ci] -= sA[(c0 + ci)*C_ + cp] * s0;
                }
            }
            if (it < 5) {
                #pragma unroll 6
                for (int ci = 0; ci < 6; ci++) {
                    if (ci >= ln) break;
                    pp[(c0 + ci)*PPW + RAD + x] = q[ci];
                }
            } else {
                #pragma unroll 6
                for (int ci = 0; ci < 6; ci++) {
                    if (ci >= ln) break;
                    out[(x*H_ + y)*C_ + c0 + ci] = q[ci];   // out[0, w, h, c]
                }
            }
        }
        if (it == 5) break;
        __syncthreads();

        // softmax per pixel over q (in pp interior)
        if (t < W_) {
            float v[C_];
            float m = -1e30f;
            #pragma unroll
            for (int c = 0; c < C_; c++) { v[c] = pp[c*PPW + RAD + t]; m = fmaxf(m, v[c]); }
            float s = 0.f;
            #pragma unroll
            for (int c = 0; c < C_; c++) { v[c] = expf(v[c] - m); s += v[c]; }
            float inv = 1.0f / s;
            #pragma unroll
            for (int c = 0; c < C_; c++) pp[c*PPW + RAD + t] = v[c] * inv;
        }
        __syncthreads();

        // hconv -> g_tmp[wb_]
        if (t < C_*22) {
            int c  = t / 22;
            int x0 = (t % 22) * 6;
            const float* p = pp + c*PPW + x0;
            float acc[6] = {0.f,0.f,0.f,0.f,0.f,0.f};
            #pragma unroll
            for (int i = 0; i < TAPS + 5; i++) {
                float v = p[i];
                #pragma unroll
                for (int r = 0; r < 6; r++) {
                    int j = i - r;
                    if (j >= 0 && j < TAPS) acc[r] += skx[j] * v;
                }
            }
            #pragma unroll
            for (int r = 0; r < 6; r++)
                if (x0 + r < W_) g_tmp[wb_][c*N_ + y*W_ + x0 + r] = acc[r];
        }
        grid_bar(base + (++bar_k), t, y);
    }
}

extern "C" void kernel_launch(void* const* d_in, const int* in_sizes, int n_in,
                              void* d_out, int out_size) {
    const float* un     = (const float*)d_in[0];
    // d_in[1] = rgb : provably unused (bilateral output discarded by replicated source bug)
    const float* ws     = (const float*)d_in[2];
    const float* wb     = (const float*)d_in[3];
    const float* compat = (const float*)d_in[4];
    float* out = (float*)d_out;

    crf_persistent<<<GRID, NTHR>>>(un, ws, wb, compat, out);
}

// round 10
// speedup vs baseline: 1.5067x; 1.0201x over previous
#include <cuda_runtime.h>
#include <math.h>

#define H_    96
#define W_    128
#define C_    21
#define N_    (H_*W_)
#define RAD   16
#define TAPS  33
#define PADH  (H_ + 2*RAD)     // 128 padded rows per channel
#define PPW   168              // padded row stride for hconv (>= 164)
#define GRID  96
#define NTB   672              // 21 warps: warp = channel
#define NTA   512

// Scratch (__device__ globals: allocation-free rule)
__device__ float g_tmp[2][C_*PADH*W_];   // halo-padded, double-buffered hconv out
__device__ float g_kx[TAPS];
__device__ float g_sinx[W_];
__device__ float g_siny[H_];
__device__ float g_A[C_*C_];             // compat @ (Ws + Wb)

// channel split over 4 groups: sizes 6,5,5,5
__device__ __forceinline__ int grp_c0(int g)  { return (g == 0) ? 0 : (1 + 5*g); }
__device__ __forceinline__ int grp_len(int g) { return (g == 0) ? 6 : 5; }

// ---------------- INIT: tables + zero halo rows of both buffers ----------------
__global__ void k_init(const float* __restrict__ ws,
                       const float* __restrict__ wb,
                       const float* __restrict__ compat)
{
    const int t = threadIdx.x, b = blockIdx.x;
    // zero halo rows: 2 buffers x 21 ch x 32 rows x 128
    const int TOT = 2*C_*2*RAD*W_;
    for (int i = b*blockDim.x + t; i < TOT; i += gridDim.x*blockDim.x) {
        int buf = i / (C_*2*RAD*W_);
        int rem = i % (C_*2*RAD*W_);
        int c  = rem / (2*RAD*W_);
        int rr = (rem / W_) % (2*RAD);
        int w  = rem % W_;
        int row = (rr < RAD) ? rr : (RAD + H_ + rr - RAD);
        g_tmp[buf][(c*PADH + row)*W_ + w] = 0.f;
    }
    if (b == 0) {
        __shared__ float skx[TAPS];
        if (t < TAPS) { skx[t] = expf(-(float)((t-RAD)*(t-RAD)) / 18.0f); g_kx[t] = skx[t]; }
        __syncthreads();
        if (t < W_) {
            float s = 0.f;
            #pragma unroll
            for (int j = 0; j < TAPS; j++) {
                int xp = t + j - RAD;
                if (xp >= 0 && xp < W_) s += skx[j];
            }
            g_sinx[t] = 1.0f / s;
        }
        if (t >= 128 && t < 128 + H_) {
            int y = t - 128;
            float s = 0.f;
            #pragma unroll
            for (int j = 0; j < TAPS; j++) {
                int yp = y + j - RAD;
                if (yp >= 0 && yp < H_) s += skx[j];
            }
            g_siny[y] = 1.0f / s;
        }
        for (int idx = t; idx < C_*C_; idx += blockDim.x) {
            int i = idx / C_, j = idx % C_;
            float a = 0.f;
            #pragma unroll
            for (int k = 0; k < C_; k++)
                a += compat[i*C_ + k] * (ws[k*C_ + j] + wb[k*C_ + j]);
            g_A[idx] = a;   // bilateral path is dead code (replicated source bug)
        }
    }
}

// shared helpers -----------------------------------------------------------
__device__ __forceinline__ void do_softmax_row(const float* src, int stride,
                                               float* pp, int x)
{   // src[c*stride + x] -> pp[c*PPW + RAD + x], softmax over c
    float v[C_];
    float m = -1e30f;
    #pragma unroll
    for (int c = 0; c < C_; c++) { v[c] = src[c*stride + x]; m = fmaxf(m, v[c]); }
    float s = 0.f;
    #pragma unroll
    for (int c = 0; c < C_; c++) { v[c] = expf(v[c] - m); s += v[c]; }
    float inv = 1.0f / s;
    #pragma unroll
    for (int c = 0; c < C_; c++) pp[c*PPW + RAD + x] = v[c] * inv;
}

__device__ __forceinline__ void do_hconv(const float* pp, const float* skx,
                                         float* dst_row_base, int t)
{   // t < C_*22; 6 outputs per thread; dst = g_tmp[buf] + (c*PADH + RAD + y)*W_
    int c  = t / 22;
    int x0 = (t % 22) * 6;
    const float* p = pp + c*PPW + x0;
    float acc[6] = {0.f,0.f,0.f,0.f,0.f,0.f};
    #pragma unroll
    for (int i = 0; i < TAPS + 5; i++) {
        float v = p[i];
        #pragma unroll
        for (int r = 0; r < 6; r++) {
            int j = i - r;
            if (j >= 0 && j < TAPS) acc[r] += skx[j] * v;
        }
    }
    #pragma unroll
    for (int r = 0; r < 6; r++)
        if (x0 + r < W_) dst_row_base[c*PADH*W_ + x0 + r] = acc[r];
}

// ---------------- A0: softmax(unaries) + hconv -> g_tmp[0] ----------------
__global__ __launch_bounds__(NTA)
void k_a0(const float* __restrict__ un)
{
    __shared__ float skx[TAPS];
    __shared__ float s_un[C_*W_];
    __shared__ float pp[C_*PPW];
    const int t = threadIdx.x, y = blockIdx.x;

    if (t < TAPS) skx[t] = g_kx[t];
    // zero hconv pads
    if (t < C_*(PPW - W_)) {
        int c = t / (PPW - W_), k = t % (PPW - W_);
        pp[c*PPW + (k < RAD ? k : W_ + k)] = 0.f;
    }
    {   // stage unaries row: un[y][x][c] -> s_un[c*W + x]
        const float* ub = un + y*W_*C_;
        for (int i = t; i < C_*W_; i += NTA) {
            int x = i / C_, c = i - x*C_;
            s_un[c*W_ + x] = ub[i];
        }
    }
    __syncthreads();
    if (t < W_) do_softmax_row(s_un, W_, pp, t);
    __syncthreads();
    if (t < C_*22) do_hconv(pp, skx, &g_tmp[0][(RAD + y)*W_], t);
}

// ------- B: vconv + update matvec (+ softmax + hconv | final out) -------
__global__ __launch_bounds__(NTB)
void k_b(const float* __restrict__ un, float* __restrict__ out,
         int rb, int final_it)
{
    __shared__ float skx[TAPS];
    __shared__ float sA[C_*C_];
    __shared__ float sinx[W_];
    __shared__ float s_un[C_*W_];
    __shared__ float s_sv[C_*W_];
    __shared__ float pp[C_*PPW];
    __shared__ float s_ny;

    const int t = threadIdx.x, y = blockIdx.x;

    if (t < TAPS) skx[t] = g_kx[t];
    if (t == NTB-1) s_ny = g_siny[y];
    if (t >= 128 && t < 256) sinx[t-128] = g_sinx[t-128];
    for (int i = t; i < C_*C_; i += NTB) sA[i] = g_A[i];
    if (!final_it && t < C_*(PPW - W_)) {
        int c = t / (PPW - W_), k = t % (PPW - W_);
        pp[c*PPW + (k < RAD ? k : W_ + k)] = 0.f;
    }
    {   // stage unaries row
        const float* ub = un + y*W_*C_;
        for (int i = t; i < C_*W_; i += NTB) {
            int x = i / C_, c = i - x*C_;
            s_un[c*W_ + x] = ub[i];
        }
    }
    __syncthreads();

    // vconv: warp = channel (21 warps), lane = float4 column. No bounds checks:
    // halo rows are zero. Output row y reads padded rows y..y+32.
    {
        const int c = t >> 5, l = t & 31;
        const int x4 = l << 2;
        const float nys = s_ny;
        const float4* src = (const float4*)&g_tmp[rb][(c*PADH + y)*W_ + x4];
        float4 acc = make_float4(0.f, 0.f, 0.f, 0.f);
        #pragma unroll
        for (int j = 0; j < TAPS; j++) {
            float4 v = src[j*(W_/4)];
            float k = skx[j];
            acc.x += k*v.x; acc.y += k*v.y; acc.z += k*v.z; acc.w += k*v.w;
        }
        s_sv[c*W_ + x4 + 0] = acc.x * (sinx[x4 + 0] * nys);
        s_sv[c*W_ + x4 + 1] = acc.y * (sinx[x4 + 1] * nys);
        s_sv[c*W_ + x4 + 2] = acc.z * (sinx[x4 + 2] * nys);
        s_sv[c*W_ + x4 + 3] = acc.w * (sinx[x4 + 3] * nys);
    }
    __syncthreads();

    // update matvec: q = u - A*s   (thread = pixel x, channel group g)
    if (t < 512) {
        const int x  = t & 127;
        const int g  = t >> 7;
        const int c0 = grp_c0(g), ln = grp_len(g);
        float q[6];
        #pragma unroll 6
        for (int ci = 0; ci < 6; ci++) {
            if (ci >= ln) break;
            q[ci] = s_un[(c0 + ci)*W_ + x];
        }
        #pragma unroll
        for (int cp = 0; cp < C_; cp++) {
            float s0 = s_sv[cp*W_ + x];
            #pragma unroll 6
            for (int ci = 0; ci < 6; ci++) {
                if (ci >= ln) break;
                q[ci] -= sA[(c0 + ci)*C_ + cp] * s0;
            }
        }
        if (final_it) {
            #pragma unroll 6
            for (int ci = 0; ci < 6; ci++) {
                if (ci >= ln) break;
                out[(x*H_ + y)*C_ + c0 + ci] = q[ci];   // out[0, w, h, c]
            }
        } else {
            #pragma unroll 6
            for (int ci = 0; ci < 6; ci++) {
                if (ci >= ln) break;
                pp[(c0 + ci)*PPW + RAD + x] = q[ci];
            }
        }
    }
    if (final_it) return;
    __syncthreads();

    // softmax over q (in pp interior), in place
    if (t < W_) {
        float v[C_];
        float m = -1e30f;
        #pragma unroll
        for (int c = 0; c < C_; c++) { v[c] = pp[c*PPW + RAD + t]; m = fmaxf(m, v[c]); }
        float s = 0.f;
        #pragma unroll
        for (int c = 0; c < C_; c++) { v[c] = expf(v[c] - m); s += v[c]; }
        float inv = 1.0f / s;
        #pragma unroll
        for (int c = 0; c < C_; c++) pp[c*PPW + RAD + t] = v[c] * inv;
    }
    __syncthreads();

    if (t < C_*22) do_hconv(pp, skx, &g_tmp[rb ^ 1][(RAD + y)*W_], t);
}

extern "C" void kernel_launch(void* const* d_in, const int* in_sizes, int n_in,
                              void* d_out, int out_size) {
    const float* un     = (const float*)d_in[0];
    // d_in[1] = rgb : provably unused (bilateral output discarded by replicated source bug)
    const float* ws     = (const float*)d_in[2];
    const float* wb     = (const float*)d_in[3];
    const float* compat = (const float*)d_in[4];
    float* out = (float*)d_out;

    k_init<<<GRID, 288>>>(ws, wb, compat);
    k_a0<<<GRID, NTA>>>(un);
    k_b<<<GRID, NTB>>>(un, out, 0, 0);   // it1: reads buf0, writes buf1
    k_b<<<GRID, NTB>>>(un, out, 1, 0);   // it2
    k_b<<<GRID, NTB>>>(un, out, 0, 0);   // it3
    k_b<<<GRID, NTB>>>(un, out, 1, 0);   // it4
    k_b<<<GRID, NTB>>>(un, out, 0, 1);   // it5 final -> out
}